// round 17
// baseline (speedup 1.0000x reference)
#include <cuda_runtime.h>
#include <cuda_fp16.h>
#include <cstdint>

#define SEQ 512
#define CHAN 512
#define NH 8
#define BATCH 32
#define NPH 2048          // n per head = 32 batch * 64 ch
#define TILE_B 16384      // one chunk tile: 128 rows x 128 bytes (swizzled)
#define NSTAGE 3
#define STAGE_BYTES (2 * TILE_B)
#define MBAR_OFF (NSTAGE * STAGE_BYTES)
#define GEMM_SMEM (MBAR_OFF + 64)

// ---------------- device globals (scratch; no allocs allowed) ----------------
__device__ __align__(16) unsigned char g_wh[NH * 4 * 8 * TILE_B];      // 4MB swizzled tiles
__device__ __align__(16) unsigned char g_xh[NH * 16 * 8 * TILE_B];     // 16MB swizzled tiles
__device__ __align__(16) __half g_outT[NH * NPH * SEQ];                // [h][n][p] fp16 16.8MB

// ---------------- helpers ----------------
__device__ __forceinline__ uint32_t smem_u32(const void* p) {
    uint32_t a;
    asm("{ .reg .u64 t; cvta.to.shared.u64 t, %1; cvt.u32.u64 %0, t; }" : "=r"(a) : "l"(p));
    return a;
}
__device__ __forceinline__ void ldsm_x4(uint32_t r[4], uint32_t addr) {
    asm volatile("ldmatrix.sync.aligned.m8n8.x4.shared.b16 {%0,%1,%2,%3}, [%4];"
                 : "=r"(r[0]), "=r"(r[1]), "=r"(r[2]), "=r"(r[3]) : "r"(addr));
}
__device__ __forceinline__ void mma_fp16(float c[4], const uint32_t a[4],
                                         const uint32_t* b) {
    asm volatile("mma.sync.aligned.m16n8k16.row.col.f32.f16.f16.f32 "
                 "{%0,%1,%2,%3}, {%4,%5,%6,%7}, {%8,%9}, {%0,%1,%2,%3};"
                 : "+f"(c[0]), "+f"(c[1]), "+f"(c[2]), "+f"(c[3])
                 : "r"(a[0]), "r"(a[1]), "r"(a[2]), "r"(a[3]), "r"(b[0]), "r"(b[1]));
}
#define MB_INIT(mb, cnt) \
    asm volatile("mbarrier.init.shared.b64 [%0], %1;" \
                 :: "r"((uint32_t)(mb)), "r"((uint32_t)(cnt)) : "memory")
#define MB_EXPECT_TX(mb, bytes) \
    asm volatile("mbarrier.arrive.expect_tx.shared.b64 _, [%0], %1;" \
                 :: "r"((uint32_t)(mb)), "r"((uint32_t)(bytes)) : "memory")
#define MB_WAIT_PARITY(mb, par) do {                                            \
    uint32_t _m = (uint32_t)(mb), _p = (uint32_t)(par), _d;                     \
    asm volatile("{\n\t.reg .pred p;\n\t"                                       \
        "mbarrier.try_wait.parity.acquire.cta.shared::cta.b64 p, [%1], %2;\n\t" \
        "selp.b32 %0, 1, 0, p;\n\t}" : "=r"(_d) : "r"(_m), "r"(_p) : "memory"); \
    if (!_d) {                                                                  \
        asm volatile("{\n\t.reg .pred P1;\n\t"                                  \
            "WL_%=:\n\t"                                                        \
            "mbarrier.try_wait.parity.acquire.cta.shared::cta.b64 P1, [%0], %1, 0x989680;\n\t" \
            "@P1 bra.uni WD_%=;\n\t"                                            \
            "bra.uni WL_%=;\n\t"                                                \
            "WD_%=:\n\t}" :: "r"(_m), "r"(_p) : "memory");                      \
    }                                                                           \
} while (0)
#define CP_BULK(dst, src, sz, mb) \
    asm volatile("cp.async.bulk.shared::cluster.global.mbarrier::complete_tx::bytes " \
                 "[%0], [%1], %2, [%3];" \
                 :: "r"((uint32_t)(dst)), "l"(src), "r"((uint32_t)(sz)), \
                    "r"((uint32_t)(mb)) : "memory")

// swizzled byte offset of granule (row, c16) inside a 16KB tile
__device__ __forceinline__ int sw_off(int row, int c16) {
    return (row * 8 + (c16 ^ (row & 7))) * 16;
}

__device__ __forceinline__ int delta_idx(int pp, int pr) {
    int d0 = (pp - pr) & 7;
    int d1 = ((pp >> 3) - (pr >> 3)) & 7;
    int d2 = ((pp >> 6) - (pr >> 6)) & 7;
    return (d2 << 6) | (d1 << 3) | d0;
}

// ---------------- kernel 1: fused x-split + W-split ----------------
// Grid (8,8,32): xsplit tile (c0, p0/ck, b). Blocks with flat id < 1024 also
// produce one 256-granule chunk of the W tiles (same gid mapping as before).
__global__ __launch_bounds__(256) void xsplit_kernel(const float* __restrict__ x,
                                                     const float* __restrict__ basis,
                                                     const float* __restrict__ kern) {
    __shared__ float s[64][65];
    __shared__ float sw[SEQ];
    const int t = threadIdx.x;
    const int c0 = blockIdx.x * 64;
    const int p0 = blockIdx.y * 64;
    const int b  = blockIdx.z;
    const int ck = blockIdx.y;      // 64 p' per ck chunk
    const int flat = blockIdx.x + 8 * blockIdx.y + 64 * blockIdx.z;
    const bool dow = flat < 1024;
    const int h_w = flat >> 7;      // == gid>>15 for gid = flat*256+t

    // phase 1a: x tile load (vectorized: 4 LDG.128/thread)
#pragma unroll
    for (int i = 0; i < 4; i++) {
        int vid = t + i * 256;              // 1024 float4 granules
        int row = vid >> 4, q = vid & 15;
        float4 v = *reinterpret_cast<const float4*>(
            x + ((size_t)(b * SEQ) + p0 + row) * CHAN + c0 + q * 4);
        s[row][q * 4 + 0] = v.x;
        s[row][q * 4 + 1] = v.y;
        s[row][q * 4 + 2] = v.z;
        s[row][q * 4 + 3] = v.w;
    }
    // phase 1b: w column for this block's W-head (identical math to old wsplit)
    if (dow) {
#pragma unroll
        for (int rep = 0; rep < 2; rep++) {
            int e = t + rep * 256;
            float acc = 0.f;
#pragma unroll
            for (int sidx = 0; sidx < 24; sidx++)
                acc = fmaf(basis[e * 24 + sidx], kern[sidx * NH + h_w], acc);
            sw[e] = acc;
        }
    }
    __syncthreads();

    // phase 2a: W granule output (bit-identical to old wsplit)
    if (dow) {
        const int gid = flat * 256 + t;
        const int c16w = gid & 7;
        const int roww = (gid >> 3) & 127;
        const int ckw  = (gid >> 10) & 7;
        const int ptw  = (gid >> 13) & 3;
        const int p    = ptw * 128 + roww;
        __align__(16) __half hb[8];
#pragma unroll
        for (int j = 0; j < 8; j++) {
            int pp = ckw * 64 + c16w * 8 + j;
            hb[j] = __float2half(sw[delta_idx(pp, p)]);
        }
        size_t off = ((size_t)((h_w * 4 + ptw) * 8 + ckw)) * TILE_B + sw_off(roww, c16w);
        *reinterpret_cast<uint4*>(g_wh + off) = *reinterpret_cast<uint4*>(hb);
    }

    // phase 2b: x-split output (unchanged)
    {
        const int cl = t >> 2;          // c local
        const int pq = t & 3;           // 16 p' each
        const int c  = c0 + cl;
        const int h  = c & 7;
        const int ch = c >> 3;
        const int n  = b * 64 + ch;
        const int nt = n >> 7;
        const int nrow = n & 127;
        const size_t tb = ((size_t)((h * 16 + nt) * 8 + ck)) * TILE_B;

#pragma unroll
        for (int g = 0; g < 2; g++) {
            int c16 = pq * 2 + g;
            __align__(16) __half hb[8];
#pragma unroll
            for (int j = 0; j < 8; j++)
                hb[j] = __float2half(s[c16 * 8 + j][cl]);
            *reinterpret_cast<uint4*>(g_xh + tb + sw_off(nrow, c16)) =
                *reinterpret_cast<uint4*>(hb);
        }
    }
}

// ---------------- kernel 2: fp16 HMMA GEMM (R14/R16 exact: 8 warps 32x64) ----------------
__global__ __launch_bounds__(256, 2) void gemm_kernel() {
    extern __shared__ __align__(16) unsigned char sm[];
    const uint32_t sb0 = smem_u32(sm);
    const int tid  = threadIdx.x;
    const int lane = tid & 31;
    const int wid  = tid >> 5;
    const int wm   = wid & 3;       // m-group: 32 p rows
    const int wn   = wid >> 2;      // n-group: 64 n cols
    const int pt = blockIdx.x, nt = blockIdx.y, h = blockIdx.z;
    const int p0 = pt * 128;
    const int n0 = nt * 128;

    const unsigned char* gA = g_wh + ((size_t)((h * 4 + pt) * 8)) * TILE_B;
    const unsigned char* gB = g_xh + ((size_t)((h * 16 + nt) * 8)) * TILE_B;

    if (tid == 0) {
#pragma unroll
        for (int st = 0; st < NSTAGE; st++) MB_INIT(sb0 + MBAR_OFF + st * 8, 1);
    }
    __syncthreads();
    if (tid == 0) {
#pragma unroll
        for (int st = 0; st < NSTAGE; st++) {
            uint32_t mb = sb0 + MBAR_OFF + st * 8;
            MB_EXPECT_TX(mb, STAGE_BYTES);
            CP_BULK(sb0 + st * STAGE_BYTES,          gA + st * TILE_B, TILE_B, mb);
            CP_BULK(sb0 + st * STAGE_BYTES + TILE_B, gB + st * TILE_B, TILE_B, mb);
        }
    }

    const int g  = lane >> 3, rr = lane & 7;
    const int a_row = wm * 32 + (g & 1) * 8 + rr;    // + mi*16
    const int a_cg  = g >> 1;                        // + 2*ks
    const int b_row = wn * 64 + (g >> 1) * 8 + rr;   // + bt*16
    const int b_cg  = g & 1;                         // + 2*ks

    float acc[2][8][4];
#pragma unroll
    for (int mi = 0; mi < 2; mi++)
#pragma unroll
        for (int ni = 0; ni < 8; ni++)
#pragma unroll
            for (int e = 0; e < 4; e++) acc[mi][ni][e] = 0.f;

    int st = 0, par = 0;
#pragma unroll 1
    for (int ck = 0; ck < 8; ck++) {
        const uint32_t mb = sb0 + MBAR_OFF + st * 8;
        MB_WAIT_PARITY(mb, par);
        const uint32_t sb = sb0 + st * STAGE_BYTES;

#pragma unroll
        for (int ks = 0; ks < 4; ks++) {
            uint32_t Af[2][4], Bf[4][4];
#pragma unroll
            for (int mi = 0; mi < 2; mi++) {
                int row = a_row + mi * 16;
                int c16 = 2 * ks + a_cg;
                ldsm_x4(Af[mi], sb + (uint32_t)sw_off(row, c16));
            }
#pragma unroll
            for (int bt = 0; bt < 4; bt++) {
                int row = b_row + bt * 16;
                int c16 = 2 * ks + b_cg;
                ldsm_x4(Bf[bt], sb + TILE_B + (uint32_t)sw_off(row, c16));
            }
#pragma unroll
            for (int mi = 0; mi < 2; mi++)
#pragma unroll
                for (int ni = 0; ni < 8; ni++)
                    mma_fp16(acc[mi][ni], Af[mi], &Bf[ni >> 1][(ni & 1) * 2]);
        }
        __syncthreads();   // all warps done with this stage buffer

        if (tid == 0 && ck + NSTAGE < 8) {
            MB_EXPECT_TX(mb, STAGE_BYTES);
            CP_BULK(sb,          gA + (ck + NSTAGE) * TILE_B, TILE_B, mb);
            CP_BULK(sb + TILE_B, gB + (ck + NSTAGE) * TILE_B, TILE_B, mb);
        }
        if (++st == NSTAGE) { st = 0; par ^= 1; }
    }

    // ---- epilogue: smem transpose then packed fp16 stores to g_outT[h][n][p] ----
    float* sf = reinterpret_cast<float*>(sm);   // [128 n][132 pad] fp32 (67.5KB < MBAR_OFF)
    {
        const int prl = wm * 32 + (lane >> 2);
        const int nll = wn * 64 + 2 * (lane & 3);
#pragma unroll
        for (int mi = 0; mi < 2; mi++)
#pragma unroll
            for (int ni = 0; ni < 8; ni++)
#pragma unroll
                for (int e = 0; e < 4; e++) {
                    int p_l = prl + mi * 16 + (e >> 1) * 8;
                    int n_l = nll + ni * 8 + (e & 1);
                    sf[n_l * 132 + p_l] = acc[mi][ni][e];
                }
    }
    __syncthreads();
    {
        const int n_l  = tid >> 1;
        const int half = tid & 1;
        const float* srcf = sf + n_l * 132 + half * 64;
        uint4* dst = reinterpret_cast<uint4*>(
            g_outT + ((size_t)(h * NPH) + n0 + n_l) * SEQ + p0 + half * 64);
#pragma unroll
        for (int i = 0; i < 8; i++) {
            float4 a = *reinterpret_cast<const float4*>(srcf + i * 8);
            float4 b4 = *reinterpret_cast<const float4*>(srcf + i * 8 + 4);
            __half2 h01 = __floats2half2_rn(a.x, a.y);
            __half2 h23 = __floats2half2_rn(a.z, a.w);
            __half2 h45 = __floats2half2_rn(b4.x, b4.y);
            __half2 h67 = __floats2half2_rn(b4.z, b4.w);
            uint4 pk;
            pk.x = *reinterpret_cast<uint32_t*>(&h01);
            pk.y = *reinterpret_cast<uint32_t*>(&h23);
            pk.z = *reinterpret_cast<uint32_t*>(&h45);
            pk.w = *reinterpret_cast<uint32_t*>(&h67);
            dst[i] = pk;
        }
    }
}

// ---------------- kernel 3: outT fp16 [h][n][p] -> out fp32 [b][p][c] ----------------
// Block tile: 64 p x 128 c (16KB smem), 1024 CTAs.
__global__ __launch_bounds__(256) void untranspose_kernel(float* __restrict__ out) {
    __shared__ __align__(16) __half sh[128 * 64];   // 16KB
    const int t = threadIdx.x;
    const int p0 = blockIdx.x * 64;
    const int c0 = blockIdx.y * 128;
    const int b  = blockIdx.z;

    // load: 4 LDG.128/thread, coalesced 128B rows of outT; granule = 8 p halves
#pragma unroll
    for (int i = 0; i < 4; i++) {
        int vid = t + i * 256;          // 1024 granules
        int cl = vid >> 3, q = vid & 7;
        int c = c0 + cl;
        int h = c & 7, ch = c >> 3;
        uint4 v = *reinterpret_cast<const uint4*>(
            g_outT + ((size_t)(h * NPH) + b * 64 + ch) * SEQ + p0 + q * 8);
        int qs = q ^ ((cl >> 2) & 7);
        *reinterpret_cast<uint4*>(sh + cl * 64 + qs * 8) = v;
    }
    __syncthreads();

    // store: task = 4 c x 8 p; 4 LDS.128 + paired converts + 8 STG.128 (fp32)
    {
        int cq = t & 31, pq = t >> 5;   // 256 tasks
        int qs = pq ^ (cq & 7);         // ((4cq+j)>>2)&7 == cq&7 for j<4
        uint4 v[4];
#pragma unroll
        for (int j = 0; j < 4; j++)
            v[j] = *reinterpret_cast<const uint4*>(sh + (4 * cq + j) * 64 + qs * 8);
#pragma unroll
        for (int pp = 0; pp < 8; pp += 2) {
            float2 f0 = __half22float2(reinterpret_cast<const __half2*>(&v[0])[pp >> 1]);
            float2 f1 = __half22float2(reinterpret_cast<const __half2*>(&v[1])[pp >> 1]);
            float2 f2 = __half22float2(reinterpret_cast<const __half2*>(&v[2])[pp >> 1]);
            float2 f3 = __half22float2(reinterpret_cast<const __half2*>(&v[3])[pp >> 1]);
            float4 oa = make_float4(f0.x, f1.x, f2.x, f3.x);
            float4 ob = make_float4(f0.y, f1.y, f2.y, f3.y);
            *reinterpret_cast<float4*>(
                out + ((size_t)(b * SEQ) + p0 + pq * 8 + pp) * CHAN + c0 + 4 * cq) = oa;
            *reinterpret_cast<float4*>(
                out + ((size_t)(b * SEQ) + p0 + pq * 8 + pp + 1) * CHAN + c0 + 4 * cq) = ob;
        }
    }
}

// ---------------- launch ----------------
extern "C" void kernel_launch(void* const* d_in, const int* in_sizes, int n_in,
                              void* d_out, int out_size) {
    const float* x = nullptr;
    const float* basis = nullptr;
    const float* kern = nullptr;
    for (int i = 0; i < n_in; i++) {
        if (in_sizes[i] == BATCH * SEQ * CHAN)      x     = (const float*)d_in[i];
        else if (in_sizes[i] == SEQ * 24)           basis = (const float*)d_in[i];
        else if (in_sizes[i] == 24 * NH)            kern  = (const float*)d_in[i];
    }
    float* out = (float*)d_out;

    cudaFuncSetAttribute(gemm_kernel,
                         cudaFuncAttributeMaxDynamicSharedMemorySize, GEMM_SMEM);

    xsplit_kernel<<<dim3(8, 8, 32), 256>>>(x, basis, kern);
    gemm_kernel<<<dim3(4, 16, NH), 256, GEMM_SMEM>>>();
    untranspose_kernel<<<dim3(8, 4, 32), 256>>>(out);
}